// round 14
// baseline (speedup 1.0000x reference)
#include <cuda_runtime.h>
#include <math.h>

// Tropical (max-plus) matmul with exact top-K candidate pruning, 2 kernels:
//   out[b,o] = max_i ( W[o,i] + X[b,i] * factors[o] )
// B=512, OUT=1024, IN=1024, fp32.
//
// Round 14: candidate SELECTION is made W-independent. K1 computes, in one
// grid: (a) W transpose + global W min/max + F stats [256 blocks], and
// (b) per-row top-4 / bottom-4 X values+indices [64 blocks, warp per row]
// — (b) needs no W info, so no sync between (a) and (b). K2 checks the
// exactness condition (all candidates provably inside top-4: kp<4, from the
// bound X[i] >= xmax - spread/f_pos_min) and does 1-2 coalesced gathers from
// WT. No X load, no smem, no barrier, no atomics in K2. f<=0 / unprovable
// cases fall back to exact scans.

#define B_DIM   512
#define OUT_DIM 1024
#define IN_DIM  1024
#define FULL    0xFFFFFFFFu

typedef unsigned int u32;

__device__ float g_WT[(size_t)IN_DIM * OUT_DIM];   // WT[i][o] = W[o][i]
// ordered-uint encoded global W extrema; static init = valid bottom/top,
// atomics re-converge to identical values on every graph replay.
__device__ u32   g_whi_key = 0u;
__device__ u32   g_wlo_key = 0xFFFFFFFFu;
__device__ float g_fposmin, g_fnegminabs;

__device__ float g_xt[B_DIM][4];   // top-4 X values, descending
__device__ int   g_xti[B_DIM][4];
__device__ float g_xb[B_DIM][4];   // bottom-4 X values, ascending
__device__ int   g_xbi[B_DIM][4];

// monotone float <-> uint encoding (float order == unsigned order)
__device__ __forceinline__ u32 fenc(float f) {
    u32 u = __float_as_uint(f);
    return (u & 0x80000000u) ? ~u : (u | 0x80000000u);
}
__device__ __forceinline__ float fdec(u32 k) {
    u32 u = (k & 0x80000000u) ? (k & 0x7FFFFFFFu) : ~k;
    return __uint_as_float(u);
}

// ---- K1: [0..255] W transpose + stats; [256..319] X top/bottom-4 ---------
__global__ __launch_bounds__(256)
void k_prep(const float* __restrict__ W,
            const float* __restrict__ F,
            const float* __restrict__ X)
{
    const int blk  = blockIdx.x;
    const int tid  = threadIdx.x;
    const int lane = tid & 31;
    const int wid  = tid >> 5;

    if (blk < 256) {
        // ------- W transpose (64x64 float4 tile) + global min/max ---------
        __shared__ float tile[64][65];
        __shared__ u32 wmax[8], wmin[8], wfp[8], wfn[8];

        const int tx4 = tid & 15;
        const int row = tid >> 4;
        const int i0  = (blk & 15) * 64;
        const int o0  = (blk >> 4) * 64;

        float lmax = -INFINITY, lmin = INFINITY;
        #pragma unroll
        for (int rr = 0; rr < 4; rr++) {
            const int r = row + rr * 16;
            const float4 v = *reinterpret_cast<const float4*>(
                W + (size_t)(o0 + r) * IN_DIM + i0 + tx4 * 4);
            tile[r][tx4 * 4 + 0] = v.x;
            tile[r][tx4 * 4 + 1] = v.y;
            tile[r][tx4 * 4 + 2] = v.z;
            tile[r][tx4 * 4 + 3] = v.w;
            lmax = fmaxf(fmaxf(fmaxf(lmax, v.x), fmaxf(v.y, v.z)), v.w);
            lmin = fminf(fminf(fminf(lmin, v.x), fminf(v.y, v.z)), v.w);
        }
        u32 kmax = __reduce_max_sync(FULL, fenc(lmax));
        u32 kmin = __reduce_min_sync(FULL, fenc(lmin));
        if (lane == 0) { wmax[wid] = kmax; wmin[wid] = kmin; }

        if (blk == 0) {  // F stats
            float fp = INFINITY, fn = INFINITY;
            #pragma unroll
            for (int j = 0; j < 4; j++) {
                float f = F[tid + j * 256];
                if (f > 0.f) fp = fminf(fp, f);
                if (f < 0.f) fn = fminf(fn, -f);
            }
            u32 kfp = __reduce_min_sync(FULL, fenc(fp));
            u32 kfn = __reduce_min_sync(FULL, fenc(fn));
            if (lane == 0) { wfp[wid] = kfp; wfn[wid] = kfn; }
        }
        __syncthreads();

        #pragma unroll
        for (int rr = 0; rr < 4; rr++) {
            const int i = row + rr * 16;
            const float4 w = make_float4(tile[tx4 * 4 + 0][i],
                                         tile[tx4 * 4 + 1][i],
                                         tile[tx4 * 4 + 2][i],
                                         tile[tx4 * 4 + 3][i]);
            *reinterpret_cast<float4*>(
                g_WT + (size_t)(i0 + i) * OUT_DIM + o0 + tx4 * 4) = w;
        }

        if (tid == 0) {
            u32 hi = wmax[0], lo = wmin[0];
            #pragma unroll
            for (int k = 1; k < 8; k++) {
                hi = max(hi, wmax[k]);
                lo = min(lo, wmin[k]);
            }
            atomicMax(&g_whi_key, hi);
            atomicMin(&g_wlo_key, lo);
            if (blk == 0) {
                u32 p = wfp[0], n = wfn[0];
                #pragma unroll
                for (int k = 1; k < 8; k++) {
                    p = min(p, wfp[k]);
                    n = min(n, wfn[k]);
                }
                g_fposmin    = fdec(p);
                g_fnegminabs = fdec(n);
            }
        }
    } else {
        // ------- per-row X top-4 / bottom-4: one warp per row -------------
        const int b = (blk - 256) * 8 + wid;   // 64 blocks x 8 warps = 512
        const float4* __restrict__ xr4 =
            reinterpret_cast<const float4*>(X + (size_t)b * IN_DIM);

        float vv[32];
        #pragma unroll
        for (int j = 0; j < 8; j++) {
            const float4 v = xr4[lane + 32 * j];
            vv[4*j+0] = v.x; vv[4*j+1] = v.y; vv[4*j+2] = v.z; vv[4*j+3] = v.w;
        }

        // ---- top-4 (descending) via 4x redux-max + clear
        float tv[4]; int ti[4];
        #pragma unroll
        for (int it = 0; it < 4; it++) {
            float lm = -INFINITY;
            #pragma unroll
            for (int e = 0; e < 32; e++) lm = fmaxf(lm, vv[e]);
            const u32 gk = __reduce_max_sync(FULL, fenc(lm));
            const float gv = fdec(gk);
            const u32 ball = __ballot_sync(FULL, lm == gv);
            const int src = __ffs(ball) - 1;
            int myidx = 0;
            if (lane == src) {
                bool done = false;
                #pragma unroll
                for (int e = 0; e < 32; e++) {
                    if (!done && vv[e] == gv) {
                        myidx = 4 * lane + 128 * (e >> 2) + (e & 3);
                        vv[e] = -INFINITY;
                        done = true;
                    }
                }
            }
            tv[it] = gv;
            ti[it] = __shfl_sync(FULL, myidx, src);
        }

        // ---- reload (top extraction clobbered 4 slots), bottom-4 ascending
        #pragma unroll
        for (int j = 0; j < 8; j++) {
            const float4 v = xr4[lane + 32 * j];
            vv[4*j+0] = v.x; vv[4*j+1] = v.y; vv[4*j+2] = v.z; vv[4*j+3] = v.w;
        }
        float bv[4]; int bi[4];
        #pragma unroll
        for (int it = 0; it < 4; it++) {
            float lm = INFINITY;
            #pragma unroll
            for (int e = 0; e < 32; e++) lm = fminf(lm, vv[e]);
            const u32 gk = __reduce_min_sync(FULL, fenc(lm));
            const float gv = fdec(gk);
            const u32 ball = __ballot_sync(FULL, lm == gv);
            const int src = __ffs(ball) - 1;
            int myidx = 0;
            if (lane == src) {
                bool done = false;
                #pragma unroll
                for (int e = 0; e < 32; e++) {
                    if (!done && vv[e] == gv) {
                        myidx = 4 * lane + 128 * (e >> 2) + (e & 3);
                        vv[e] = INFINITY;
                        done = true;
                    }
                }
            }
            bv[it] = gv;
            bi[it] = __shfl_sync(FULL, myidx, src);
        }

        if (lane == 0) {
            #pragma unroll
            for (int it = 0; it < 4; it++) {
                g_xt[b][it]  = tv[it];  g_xti[b][it] = ti[it];
                g_xb[b][it]  = bv[it];  g_xbi[b][it] = bi[it];
            }
        }
    }
}

// ---- K2: pure gather - no X load, no smem, no barrier, no atomics --------
__global__ __launch_bounds__(256)
void k_out(const float* __restrict__ X,
           const float* __restrict__ F,
           float* __restrict__ out)
{
    const int b   = blockIdx.x;
    const int tid = threadIdx.x;          // float4 output index
    const int o   = tid * 4;

    // uniform L2 loads
    const float spread = fdec(g_whi_key) - fdec(g_wlo_key);
    const float fpm = g_fposmin, fnm = g_fnegminabs;

    float xt[4], xb[4];
    int   xti[4], xbi[4];
    #pragma unroll
    for (int j = 0; j < 4; j++) {
        xt[j] = g_xt[b][j]; xti[j] = g_xti[b][j];
        xb[j] = g_xb[b][j]; xbi[j] = g_xbi[b][j];
    }

    const float tpos = isinf(fpm) ?  INFINITY : xt[0] - spread / fpm;
    const float tneg = isinf(fnm) ? -INFINITY : xb[0] + spread / fnm;

    // xt descending / xb ascending -> counts are prefix lengths
    int kp = 0, kn = 0;
    #pragma unroll
    for (int j = 0; j < 4; j++) {
        kp += (xt[j] >= tpos) ? 1 : 0;
        kn += (xb[j] <= tneg) ? 1 : 0;
    }
    // exact iff kp<4 (all candidates provably inside top-4); same for kn.

    const float4 f4 = reinterpret_cast<const float4*>(F)[tid];
    float4 acc = make_float4(-INFINITY, -INFINITY, -INFINITY, -INFINITY);

    const bool allpos = (f4.x > 0.f) & (f4.y > 0.f) & (f4.z > 0.f) & (f4.w > 0.f);

    if (allpos && kp < 4) {
        #pragma unroll 2
        for (int j = 0; j < kp; j++) {
            const float cx = xt[j];
            const float4 wv = reinterpret_cast<const float4*>(
                g_WT + (size_t)xti[j] * OUT_DIM)[tid];         // coalesced
            acc.x = fmaxf(acc.x, fmaf(cx, f4.x, wv.x));
            acc.y = fmaxf(acc.y, fmaf(cx, f4.y, wv.y));
            acc.z = fmaxf(acc.z, fmaf(cx, f4.z, wv.z));
            acc.w = fmaxf(acc.w, fmaf(cx, f4.w, wv.w));
        }
    } else {
        // general exact path per component
        float a[4] = {-INFINITY, -INFINITY, -INFINITY, -INFINITY};
        const float ff[4] = {f4.x, f4.y, f4.z, f4.w};
        const float* __restrict__ xrow = X + (size_t)b * IN_DIM;
        #pragma unroll
        for (int c = 0; c < 4; c++) {
            const float f = ff[c];
            float r = -INFINITY;
            if (f > 0.f && kp < 4) {
                for (int j = 0; j < kp; j++)
                    r = fmaxf(r, fmaf(xt[j], f,
                               g_WT[(size_t)xti[j] * OUT_DIM + o + c]));
            } else if (f < 0.f && kn < 4) {
                for (int j = 0; j < kn; j++)
                    r = fmaxf(r, fmaf(xb[j], f,
                               g_WT[(size_t)xbi[j] * OUT_DIM + o + c]));
            } else {
                // dense exact fallback (f == 0 or unprovable coverage)
                for (int i = 0; i < IN_DIM; i++)
                    r = fmaxf(r, fmaf(xrow[i], f,
                               g_WT[(size_t)i * OUT_DIM + o + c]));
            }
            a[c] = r;
        }
        acc = make_float4(a[0], a[1], a[2], a[3]);
    }

    reinterpret_cast<float4*>(out + (size_t)b * OUT_DIM)[tid] = acc;
}

extern "C" void kernel_launch(void* const* d_in, const int* in_sizes, int n_in,
                              void* d_out, int out_size)
{
    const float* X = (const float*)d_in[0];   // (512, 1024)
    const float* W = (const float*)d_in[1];   // (1024, 1024)
    const float* F = (const float*)d_in[2];   // (1024, 1)
    float* out = (float*)d_out;               // (512, 1024)

    k_prep<<<320, 256>>>(W, F, X);            // 256 transpose + 64 top-K
    k_out<<<B_DIM, 256>>>(X, F, out);
}

// round 15
// speedup vs baseline: 12.9240x; 12.9240x over previous
#include <cuda_runtime.h>
#include <math.h>

// Tropical (max-plus) matmul with exact top-K candidate pruning, 2 kernels:
//   out[b,o] = max_i ( W[o,i] + X[b,i] * factors[o] )
// B=512, OUT=1024, IN=1024, fp32.
//
// Round 15: R14's kp<4 proof failed on rows with clustered top values and
// fell into a catastrophic dense path (353us). Fix: top-8/bottom-8 proof
// margin, and the unprovable case now runs the R13 select+gather path
// (graceful ~7.5us worst case) instead of the per-component dense scan.

#define B_DIM   512
#define OUT_DIM 1024
#define IN_DIM  1024
#define NTOP    8
#define CAP     64
#define FULL    0xFFFFFFFFu

typedef unsigned int u32;

__device__ float g_WT[(size_t)IN_DIM * OUT_DIM];   // WT[i][o] = W[o][i]
// ordered-uint encoded global W extrema; static init = valid bottom/top,
// atomics re-converge to identical values on every graph replay.
__device__ u32   g_whi_key = 0u;
__device__ u32   g_wlo_key = 0xFFFFFFFFu;
__device__ float g_fposmin, g_fnegminabs;

__device__ float g_xt[B_DIM][NTOP];   // top-8 X values, descending
__device__ int   g_xti[B_DIM][NTOP];
__device__ float g_xb[B_DIM][NTOP];   // bottom-8 X values, ascending
__device__ int   g_xbi[B_DIM][NTOP];

// monotone float <-> uint encoding (float order == unsigned order)
__device__ __forceinline__ u32 fenc(float f) {
    u32 u = __float_as_uint(f);
    return (u & 0x80000000u) ? ~u : (u | 0x80000000u);
}
__device__ __forceinline__ float fdec(u32 k) {
    u32 u = (k & 0x80000000u) ? (k & 0x7FFFFFFFu) : ~k;
    return __uint_as_float(u);
}

// ---- K1: [0..255] W transpose + stats; [256..319] X top/bottom-8 ---------
__global__ __launch_bounds__(256)
void k_prep(const float* __restrict__ W,
            const float* __restrict__ F,
            const float* __restrict__ X)
{
    const int blk  = blockIdx.x;
    const int tid  = threadIdx.x;
    const int lane = tid & 31;
    const int wid  = tid >> 5;

    if (blk < 256) {
        // ------- W transpose (64x64 float4 tile) + global min/max ---------
        __shared__ float tile[64][65];
        __shared__ u32 wmax[8], wmin[8], wfp[8], wfn[8];

        const int tx4 = tid & 15;
        const int row = tid >> 4;
        const int i0  = (blk & 15) * 64;
        const int o0  = (blk >> 4) * 64;

        float lmax = -INFINITY, lmin = INFINITY;
        #pragma unroll
        for (int rr = 0; rr < 4; rr++) {
            const int r = row + rr * 16;
            const float4 v = *reinterpret_cast<const float4*>(
                W + (size_t)(o0 + r) * IN_DIM + i0 + tx4 * 4);
            tile[r][tx4 * 4 + 0] = v.x;
            tile[r][tx4 * 4 + 1] = v.y;
            tile[r][tx4 * 4 + 2] = v.z;
            tile[r][tx4 * 4 + 3] = v.w;
            lmax = fmaxf(fmaxf(fmaxf(lmax, v.x), fmaxf(v.y, v.z)), v.w);
            lmin = fminf(fminf(fminf(lmin, v.x), fminf(v.y, v.z)), v.w);
        }
        u32 kmax = __reduce_max_sync(FULL, fenc(lmax));
        u32 kmin = __reduce_min_sync(FULL, fenc(lmin));
        if (lane == 0) { wmax[wid] = kmax; wmin[wid] = kmin; }

        if (blk == 0) {  // F stats
            float fp = INFINITY, fn = INFINITY;
            #pragma unroll
            for (int j = 0; j < 4; j++) {
                float f = F[tid + j * 256];
                if (f > 0.f) fp = fminf(fp, f);
                if (f < 0.f) fn = fminf(fn, -f);
            }
            u32 kfp = __reduce_min_sync(FULL, fenc(fp));
            u32 kfn = __reduce_min_sync(FULL, fenc(fn));
            if (lane == 0) { wfp[wid] = kfp; wfn[wid] = kfn; }
        }
        __syncthreads();

        #pragma unroll
        for (int rr = 0; rr < 4; rr++) {
            const int i = row + rr * 16;
            const float4 w = make_float4(tile[tx4 * 4 + 0][i],
                                         tile[tx4 * 4 + 1][i],
                                         tile[tx4 * 4 + 2][i],
                                         tile[tx4 * 4 + 3][i]);
            *reinterpret_cast<float4*>(
                g_WT + (size_t)(i0 + i) * OUT_DIM + o0 + tx4 * 4) = w;
        }

        if (tid == 0) {
            u32 hi = wmax[0], lo = wmin[0];
            #pragma unroll
            for (int k = 1; k < 8; k++) {
                hi = max(hi, wmax[k]);
                lo = min(lo, wmin[k]);
            }
            atomicMax(&g_whi_key, hi);
            atomicMin(&g_wlo_key, lo);
            if (blk == 0) {
                u32 p = wfp[0], n = wfn[0];
                #pragma unroll
                for (int k = 1; k < 8; k++) {
                    p = min(p, wfp[k]);
                    n = min(n, wfn[k]);
                }
                g_fposmin    = fdec(p);
                g_fnegminabs = fdec(n);
            }
        }
    } else {
        // ------- per-row X top-8 / bottom-8: one warp per row -------------
        const int b = (blk - 256) * 8 + wid;   // 64 blocks x 8 warps = 512
        const float4* __restrict__ xr4 =
            reinterpret_cast<const float4*>(X + (size_t)b * IN_DIM);

        float vv[32];
        #pragma unroll
        for (int j = 0; j < 8; j++) {
            const float4 v = xr4[lane + 32 * j];
            vv[4*j+0] = v.x; vv[4*j+1] = v.y; vv[4*j+2] = v.z; vv[4*j+3] = v.w;
        }

        // top-8 (descending) via 8x redux-max + clear-one-occurrence
        #pragma unroll
        for (int it = 0; it < NTOP; it++) {
            float lm = -INFINITY;
            #pragma unroll
            for (int e = 0; e < 32; e++) lm = fmaxf(lm, vv[e]);
            const float gv = fdec(__reduce_max_sync(FULL, fenc(lm)));
            const u32 ball = __ballot_sync(FULL, lm == gv);
            const int src = __ffs(ball) - 1;
            int myidx = 0;
            if (lane == src) {
                bool done = false;
                #pragma unroll
                for (int e = 0; e < 32; e++) {
                    if (!done && vv[e] == gv) {
                        myidx = 4 * lane + 128 * (e >> 2) + (e & 3);
                        vv[e] = -INFINITY;
                        done = true;
                    }
                }
            }
            const int gi = __shfl_sync(FULL, myidx, src);
            if (lane == 0) { g_xt[b][it] = gv; g_xti[b][it] = gi; }
        }

        // reload and extract bottom-8 (ascending)
        #pragma unroll
        for (int j = 0; j < 8; j++) {
            const float4 v = xr4[lane + 32 * j];
            vv[4*j+0] = v.x; vv[4*j+1] = v.y; vv[4*j+2] = v.z; vv[4*j+3] = v.w;
        }
        #pragma unroll
        for (int it = 0; it < NTOP; it++) {
            float lm = INFINITY;
            #pragma unroll
            for (int e = 0; e < 32; e++) lm = fminf(lm, vv[e]);
            const float gv = fdec(__reduce_min_sync(FULL, fenc(lm)));
            const u32 ball = __ballot_sync(FULL, lm == gv);
            const int src = __ffs(ball) - 1;
            int myidx = 0;
            if (lane == src) {
                bool done = false;
                #pragma unroll
                for (int e = 0; e < 32; e++) {
                    if (!done && vv[e] == gv) {
                        myidx = 4 * lane + 128 * (e >> 2) + (e & 3);
                        vv[e] = INFINITY;
                        done = true;
                    }
                }
            }
            const int gi = __shfl_sync(FULL, myidx, src);
            if (lane == 0) { g_xb[b][it] = gv; g_xbi[b][it] = gi; }
        }
    }
}

// ---- K2: provable -> pure gather; else -> R13 select path -----------------
__global__ __launch_bounds__(256)
void k_out(const float* __restrict__ X,
           const float* __restrict__ F,
           float* __restrict__ out)
{
    __shared__ float s_x[IN_DIM];
    __shared__ float s_cx[CAP], s_cnx[CAP];
    __shared__ int   s_ci[CAP], s_cni[CAP];
    __shared__ int   cp_s, cn_s;

    const int b   = blockIdx.x;
    const int tid = threadIdx.x;          // float4 output index
    const int o   = tid * 4;

    const float spread = fdec(g_whi_key) - fdec(g_wlo_key);
    const float fpm = g_fposmin, fnm = g_fnegminabs;
    const float tpos = isinf(fpm) ?  INFINITY : g_xt[b][0] - spread / fpm;
    const float tneg = isinf(fnm) ? -INFINITY : g_xb[b][0] + spread / fnm;

    // prefix counts over sorted lists (block-uniform)
    int kp = 0, kn = 0;
    #pragma unroll
    for (int j = 0; j < NTOP; j++) {
        kp += (g_xt[b][j] >= tpos) ? 1 : 0;
        kn += (g_xb[b][j] <= tneg) ? 1 : 0;
    }

    const float4 f4 = reinterpret_cast<const float4*>(F)[tid];
    float4 acc = make_float4(-INFINITY, -INFINITY, -INFINITY, -INFINITY);

    if (kp < NTOP && kn < NTOP) {
        // -------- provable: candidates are exactly the list prefixes ------
        const bool allpos = (f4.x > 0.f) & (f4.y > 0.f) & (f4.z > 0.f) & (f4.w > 0.f);
        if (allpos) {
            for (int j = 0; j < kp; j++) {
                const float cx = g_xt[b][j];                   // uniform L2
                const float4 wv = reinterpret_cast<const float4*>(
                    g_WT + (size_t)g_xti[b][j] * OUT_DIM)[tid]; // coalesced
                acc.x = fmaxf(acc.x, fmaf(cx, f4.x, wv.x));
                acc.y = fmaxf(acc.y, fmaf(cx, f4.y, wv.y));
                acc.z = fmaxf(acc.z, fmaf(cx, f4.z, wv.z));
                acc.w = fmaxf(acc.w, fmaf(cx, f4.w, wv.w));
            }
        } else {
            float a[4] = {-INFINITY, -INFINITY, -INFINITY, -INFINITY};
            const float ff[4] = {f4.x, f4.y, f4.z, f4.w};
            #pragma unroll
            for (int c = 0; c < 4; c++) {
                const float f = ff[c];
                float r = -INFINITY;
                if (f > 0.f) {
                    for (int j = 0; j < kp; j++)
                        r = fmaxf(r, fmaf(g_xt[b][j], f,
                                   g_WT[(size_t)g_xti[b][j] * OUT_DIM + o + c]));
                } else if (f < 0.f) {
                    for (int j = 0; j < kn; j++)
                        r = fmaxf(r, fmaf(g_xb[b][j], f,
                                   g_WT[(size_t)g_xbi[b][j] * OUT_DIM + o + c]));
                } else {
                    // f == 0: out = max_i W[o,i] (exact; rare)
                    for (int i = 0; i < IN_DIM; i++)
                        r = fmaxf(r, g_WT[(size_t)i * OUT_DIM + o + c]);
                }
                a[c] = r;
            }
            acc = make_float4(a[0], a[1], a[2], a[3]);
        }
    } else {
        // -------- unprovable (rare): R13 select+gather, CAP=64 ------------
        if (tid == 0) { cp_s = 0; cn_s = 0; }
        const float4 v4 =
            reinterpret_cast<const float4*>(X + (size_t)b * IN_DIM)[tid];
        reinterpret_cast<float4*>(s_x)[tid] = v4;
        __syncthreads();   // counters zeroed + s_x visible

        const float vals[4] = {v4.x, v4.y, v4.z, v4.w};
        #pragma unroll
        for (int c = 0; c < 4; c++) {
            const float v = vals[c];
            if (v >= tpos) {
                int s = atomicAdd(&cp_s, 1);
                if (s < CAP) { s_ci[s] = 4 * tid + c; s_cx[s] = v; }
            }
            if (v <= tneg) {
                int s = atomicAdd(&cn_s, 1);
                if (s < CAP) { s_cni[s] = 4 * tid + c; s_cnx[s] = v; }
            }
        }
        __syncthreads();

        const int cp = cp_s, cn = cn_s;
        float a[4] = {-INFINITY, -INFINITY, -INFINITY, -INFINITY};
        const float ff[4] = {f4.x, f4.y, f4.z, f4.w};
        #pragma unroll
        for (int c = 0; c < 4; c++) {
            const float f = ff[c];
            float r = -INFINITY;
            if (f > 0.f && cp <= CAP) {
                for (int k = 0; k < cp; k++)
                    r = fmaxf(r, fmaf(s_cx[k], f,
                               g_WT[(size_t)s_ci[k] * OUT_DIM + o + c]));
            } else if (f < 0.f && cn <= CAP) {
                for (int k = 0; k < cn; k++)
                    r = fmaxf(r, fmaf(s_cnx[k], f,
                               g_WT[(size_t)s_cni[k] * OUT_DIM + o + c]));
            } else {
                // dense exact fallback (f == 0 or overflow)
                for (int i = 0; i < IN_DIM; i++)
                    r = fmaxf(r, fmaf(s_x[i], f,
                               g_WT[(size_t)i * OUT_DIM + o + c]));
            }
            a[c] = r;
        }
        acc = make_float4(a[0], a[1], a[2], a[3]);
    }

    reinterpret_cast<float4*>(out + (size_t)b * OUT_DIM)[tid] = acc;
}

extern "C" void kernel_launch(void* const* d_in, const int* in_sizes, int n_in,
                              void* d_out, int out_size)
{
    const float* X = (const float*)d_in[0];   // (512, 1024)
    const float* W = (const float*)d_in[1];   // (1024, 1024)
    const float* F = (const float*)d_in[2];   // (1024, 1)
    float* out = (float*)d_out;               // (512, 1024)

    k_prep<<<320, 256>>>(W, F, X);            // 256 transpose + 64 top-K
    k_out<<<B_DIM, 256>>>(X, F, out);
}

// round 16
// speedup vs baseline: 27.6942x; 2.1429x over previous
#include <cuda_runtime.h>
#include <math.h>

// Tropical (max-plus) matmul with exact candidate pruning — SINGLE KERNEL:
//   out[b,o] = max_i ( W[o,i] + X[b,i] * factors[o] )
// B=512, OUT=1024, IN=1024, fp32.
//
// For f>0 the argmax i must satisfy X[b,i] >= Xmax[b] - (Whi-Wlo)/f_pos_min
// (exact). Symmetric for f<0; f==0 / overflow -> exact dense fallbacks.
//
// Round 16: one launch. Blocks 0..255 transpose W (64x64 float4 tiles) +
// global W min/max + F stats, then signal g_done. Blocks 256..511 (2 batch
// rows each) overlap X load + row extrema with the transpose, spin on
// g_done==256 (software grid barrier), then select + gather + store.
// Residency of all 512 blocks is guaranteed (launch_bounds(256,4): regs<=64,
// smem 16.8KB -> >=4 blocks/SM -> 608 slots >= 512), so the spin cannot
// deadlock. Counters self-reset each launch -> graph-replay deterministic.

#define B_DIM   512
#define OUT_DIM 1024
#define IN_DIM  1024
#define CAP     64
#define FULL    0xFFFFFFFFu
#define NBLK_T  256
#define NBLK_B  256                 // each handles 2 batch rows
#define NBLK    (NBLK_T + NBLK_B)   // 512

typedef unsigned int u32;

__device__ float g_WT[(size_t)IN_DIM * OUT_DIM];   // WT[i][o] = W[o][i]
// ordered-uint encoded global W extrema; static init = valid bottom/top,
// atomics re-converge to identical values on every graph replay.
__device__ u32   g_whi_key = 0u;
__device__ u32   g_wlo_key = 0xFFFFFFFFu;
__device__ float g_fposmin, g_fnegminabs;
__device__ int   g_done = 0;   // transpose blocks finished (reset each launch)
__device__ int   g_fin  = 0;   // compute blocks finished  (reset each launch)

// monotone float <-> uint encoding (float order == unsigned order)
__device__ __forceinline__ u32 fenc(float f) {
    u32 u = __float_as_uint(f);
    return (u & 0x80000000u) ? ~u : (u | 0x80000000u);
}
__device__ __forceinline__ float fdec(u32 k) {
    u32 u = (k & 0x80000000u) ? (k & 0x7FFFFFFFu) : ~k;
    return __uint_as_float(u);
}

struct SmemT {                       // transpose blocks
    float tile[64][65];
    u32 wmax[8], wmin[8], wfp[8], wfn[8];
};
struct SmemB {                       // compute blocks (2 rows)
    float x[2][IN_DIM];
    float cx[2][CAP], cnx[2][CAP];
    int   ci[2][CAP], cni[2][CAP];
    int   cp[2], cn[2];
    u32   rmax[8], rmin[8];
    float tpos[2], tneg[2];
};
union SmemU { SmemT t; SmemB b; };   // 16.8KB

__global__ __launch_bounds__(256, 4)
void k_all(const float* __restrict__ X,
           const float* __restrict__ W,
           const float* __restrict__ F,
           float* __restrict__ out)
{
    __shared__ SmemU sm;
    const int blk  = blockIdx.x;
    const int tid  = threadIdx.x;
    const int lane = tid & 31;
    const int wid  = tid >> 5;

    if (blk < NBLK_T) {
        // ============ W transpose (64x64 float4) + stats ============
        const int tx4 = tid & 15;
        const int row = tid >> 4;
        const int i0  = (blk & 15) * 64;
        const int o0  = (blk >> 4) * 64;

        float lmax = -INFINITY, lmin = INFINITY;
        #pragma unroll
        for (int rr = 0; rr < 4; rr++) {
            const int r = row + rr * 16;
            const float4 v = *reinterpret_cast<const float4*>(
                W + (size_t)(o0 + r) * IN_DIM + i0 + tx4 * 4);
            sm.t.tile[r][tx4 * 4 + 0] = v.x;
            sm.t.tile[r][tx4 * 4 + 1] = v.y;
            sm.t.tile[r][tx4 * 4 + 2] = v.z;
            sm.t.tile[r][tx4 * 4 + 3] = v.w;
            lmax = fmaxf(fmaxf(fmaxf(lmax, v.x), fmaxf(v.y, v.z)), v.w);
            lmin = fminf(fminf(fminf(lmin, v.x), fminf(v.y, v.z)), v.w);
        }
        u32 kmax = __reduce_max_sync(FULL, fenc(lmax));
        u32 kmin = __reduce_min_sync(FULL, fenc(lmin));
        if (lane == 0) { sm.t.wmax[wid] = kmax; sm.t.wmin[wid] = kmin; }

        if (blk == 0) {  // F stats
            float fp = INFINITY, fn = INFINITY;
            #pragma unroll
            for (int j = 0; j < 4; j++) {
                float f = F[tid + j * 256];
                if (f > 0.f) fp = fminf(fp, f);
                if (f < 0.f) fn = fminf(fn, -f);
            }
            u32 kfp = __reduce_min_sync(FULL, fenc(fp));
            u32 kfn = __reduce_min_sync(FULL, fenc(fn));
            if (lane == 0) { sm.t.wfp[wid] = kfp; sm.t.wfn[wid] = kfn; }
        }
        __syncthreads();

        #pragma unroll
        for (int rr = 0; rr < 4; rr++) {
            const int i = row + rr * 16;
            const float4 w = make_float4(sm.t.tile[tx4 * 4 + 0][i],
                                         sm.t.tile[tx4 * 4 + 1][i],
                                         sm.t.tile[tx4 * 4 + 2][i],
                                         sm.t.tile[tx4 * 4 + 3][i]);
            *reinterpret_cast<float4*>(
                g_WT + (size_t)(i0 + i) * OUT_DIM + o0 + tx4 * 4) = w;
        }
        __threadfence();    // my WT stores ordered before the block signal
        __syncthreads();    // all threads fenced before tid0 signals

        if (tid == 0) {
            u32 hi = sm.t.wmax[0], lo = sm.t.wmin[0];
            #pragma unroll
            for (int k = 1; k < 8; k++) {
                hi = max(hi, sm.t.wmax[k]);
                lo = min(lo, sm.t.wmin[k]);
            }
            atomicMax(&g_whi_key, hi);
            atomicMin(&g_wlo_key, lo);
            if (blk == 0) {
                u32 p = sm.t.wfp[0], n = sm.t.wfn[0];
                #pragma unroll
                for (int k = 1; k < 8; k++) {
                    p = min(p, sm.t.wfp[k]);
                    n = min(n, sm.t.wfn[k]);
                }
                g_fposmin    = fdec(p);
                g_fnegminabs = fdec(n);
            }
            __threadfence();
            atomicAdd(&g_done, 1);
        }
    } else {
        // ============ compute: 2 batch rows per block ============
        const int sub  = tid >> 7;          // 0/1: which row
        const int stid = tid & 127;
        const int b    = (blk - NBLK_T) * 2 + sub;

        // W-independent phase (overlaps with transpose blocks)
        const float4* __restrict__ X4 =
            reinterpret_cast<const float4*>(X + (size_t)b * IN_DIM);
        const float4 xa = X4[stid];
        const float4 xb = X4[stid + 128];
        reinterpret_cast<float4*>(sm.b.x[sub])[stid]       = xa;
        reinterpret_cast<float4*>(sm.b.x[sub])[stid + 128] = xb;

        const float4* __restrict__ F4 = reinterpret_cast<const float4*>(F);
        const float4 fa = F4[stid];
        const float4 fb = F4[stid + 128];

        float mx = fmaxf(fmaxf(fmaxf(xa.x, xa.y), fmaxf(xa.z, xa.w)),
                         fmaxf(fmaxf(xb.x, xb.y), fmaxf(xb.z, xb.w)));
        float mn = fminf(fminf(fminf(xa.x, xa.y), fminf(xa.z, xa.w)),
                         fminf(fminf(xb.x, xb.y), fminf(xb.z, xb.w)));
        u32 kx = __reduce_max_sync(FULL, fenc(mx));
        u32 km = __reduce_min_sync(FULL, fenc(mn));
        if (lane == 0) { sm.b.rmax[wid] = kx; sm.b.rmin[wid] = km; }
        if (tid < 2) { sm.b.cp[tid] = 0; sm.b.cn[tid] = 0; }
        __syncthreads();

        // software grid barrier: wait for all transpose blocks
        if (tid == 0) {
            while (atomicAdd(&g_done, 0) < NBLK_T) __nanosleep(64);
            __threadfence();
            const float spread = fdec(g_whi_key) - fdec(g_wlo_key);
            const float fpm = g_fposmin, fnm = g_fnegminabs;
            #pragma unroll
            for (int h = 0; h < 2; h++) {
                u32 hi = sm.b.rmax[h * 4], lo = sm.b.rmin[h * 4];
                #pragma unroll
                for (int k = 1; k < 4; k++) {
                    hi = max(hi, sm.b.rmax[h * 4 + k]);
                    lo = min(lo, sm.b.rmin[h * 4 + k]);
                }
                sm.b.tpos[h] = isinf(fpm) ?  INFINITY : fdec(hi) - spread / fpm;
                sm.b.tneg[h] = isinf(fnm) ? -INFINITY : fdec(lo) + spread / fnm;
            }
        }
        __syncthreads();

        // candidate select (exact, inclusive thresholds)
        const float tpos = sm.b.tpos[sub], tneg = sm.b.tneg[sub];
        const float vals[8] = {xa.x, xa.y, xa.z, xa.w, xb.x, xb.y, xb.z, xb.w};
        #pragma unroll
        for (int c = 0; c < 8; c++) {
            const int gi = (c < 4) ? (stid * 4 + c) : ((stid + 128) * 4 + (c - 4));
            const float v = vals[c];
            if (v >= tpos) {
                int s = atomicAdd(&sm.b.cp[sub], 1);
                if (s < CAP) { sm.b.ci[sub][s] = gi; sm.b.cx[sub][s] = v; }
            }
            if (v <= tneg) {
                int s = atomicAdd(&sm.b.cn[sub], 1);
                if (s < CAP) { sm.b.cni[sub][s] = gi; sm.b.cnx[sub][s] = v; }
            }
        }
        __syncthreads();

        const int cp = sm.b.cp[sub], cn = sm.b.cn[sub];
        float4 acc0 = make_float4(-INFINITY, -INFINITY, -INFINITY, -INFINITY);
        float4 acc1 = acc0;

        const bool allpos = (fa.x > 0.f) & (fa.y > 0.f) & (fa.z > 0.f) & (fa.w > 0.f) &
                            (fb.x > 0.f) & (fb.y > 0.f) & (fb.z > 0.f) & (fb.w > 0.f);

        if (allpos && cp <= CAP) {
            for (int k = 0; k < cp; k++) {
                const float cx = sm.b.cx[sub][k];
                const float4* __restrict__ wr = reinterpret_cast<const float4*>(
                    g_WT + (size_t)sm.b.ci[sub][k] * OUT_DIM);
                const float4 w0 = wr[stid];
                const float4 w1 = wr[stid + 128];
                acc0.x = fmaxf(acc0.x, fmaf(cx, fa.x, w0.x));
                acc0.y = fmaxf(acc0.y, fmaf(cx, fa.y, w0.y));
                acc0.z = fmaxf(acc0.z, fmaf(cx, fa.z, w0.z));
                acc0.w = fmaxf(acc0.w, fmaf(cx, fa.w, w0.w));
                acc1.x = fmaxf(acc1.x, fmaf(cx, fb.x, w1.x));
                acc1.y = fmaxf(acc1.y, fmaf(cx, fb.y, w1.y));
                acc1.z = fmaxf(acc1.z, fmaf(cx, fb.z, w1.z));
                acc1.w = fmaxf(acc1.w, fmaf(cx, fb.w, w1.w));
            }
        } else {
            // general exact path per output component
            float a[8];
            const float ff[8] = {fa.x, fa.y, fa.z, fa.w, fb.x, fb.y, fb.z, fb.w};
            #pragma unroll
            for (int c = 0; c < 8; c++) {
                const int o = (c < 4) ? (stid * 4 + c) : ((stid + 128) * 4 + (c - 4));
                const float f = ff[c];
                float r = -INFINITY;
                if (f > 0.f && cp <= CAP) {
                    for (int k = 0; k < cp; k++)
                        r = fmaxf(r, fmaf(sm.b.cx[sub][k], f,
                                   g_WT[(size_t)sm.b.ci[sub][k] * OUT_DIM + o]));
                } else if (f < 0.f && cn <= CAP) {
                    for (int k = 0; k < cn; k++)
                        r = fmaxf(r, fmaf(sm.b.cnx[sub][k], f,
                                   g_WT[(size_t)sm.b.cni[sub][k] * OUT_DIM + o]));
                } else {
                    // dense exact fallback (f == 0 or overflow)
                    for (int i = 0; i < IN_DIM; i++)
                        r = fmaxf(r, fmaf(sm.b.x[sub][i], f,
                                   g_WT[(size_t)i * OUT_DIM + o]));
                }
                a[c] = r;
            }
            acc0 = make_float4(a[0], a[1], a[2], a[3]);
            acc1 = make_float4(a[4], a[5], a[6], a[7]);
        }

        float4* __restrict__ O4 = reinterpret_cast<float4*>(out + (size_t)b * OUT_DIM);
        O4[stid]       = acc0;
        O4[stid + 128] = acc1;

        // self-reset of the software barrier (last compute block)
        __threadfence();
        __syncthreads();
        if (tid == 0) {
            if (atomicAdd(&g_fin, 1) == NBLK_B - 1) {
                atomicExch(&g_done, 0);
                atomicExch(&g_fin, 0);
            }
        }
    }
}

extern "C" void kernel_launch(void* const* d_in, const int* in_sizes, int n_in,
                              void* d_out, int out_size)
{
    const float* X = (const float*)d_in[0];   // (512, 1024)
    const float* W = (const float*)d_in[1];   // (1024, 1024)
    const float* F = (const float*)d_in[2];   // (1024, 1)
    float* out = (float*)d_out;               // (512, 1024)

    k_all<<<NBLK, 256>>>(X, W, F, out);       // single launch, no gaps
}